// round 1
// baseline (speedup 1.0000x reference)
#include <cuda_runtime.h>
#include <stdint.h>

#define BLOCK_SIZE 64
#define NUM_SELECTED 16
#define NB 128          // blocks per batch (8192/64)
#define B 32
#define D 512
#define S 8192

// scratch for selected block indices (no device allocation allowed)
__device__ int g_sel[B * NUM_SELECTED];

// One CTA per batch. Exact rank-based top-k matching jax.lax.top_k ordering:
// descending by value, ties broken by lower index.
__global__ void topk_kernel(const float* __restrict__ scores) {
    int b = blockIdx.x;
    int i = threadIdx.x;  // 0..127
    __shared__ float s[NB];
    float v = scores[b * NB + i];
    s[i] = v;
    __syncthreads();
    int rank = 0;
#pragma unroll 8
    for (int j = 0; j < NB; j++) {
        float sj = s[j];
        rank += (sj > v) || (sj == v && j < i);
    }
    if (rank < NUM_SELECTED) {
        g_sel[b * NUM_SELECTED + rank] = i;
    }
}

// One CTA per output row (b, k, t): copy 512 floats = 128 float4.
// grid = 32*16*64 = 32768 CTAs, 128 threads each.
__global__ void gather_kernel(const float4* __restrict__ keys,
                              float4* __restrict__ out) {
    int row = blockIdx.x;              // 0..32767
    int b = row >> 10;                 // 1024 rows per batch
    int r = row & 1023;
    int k = r >> 6;
    int t = r & 63;
    int blk = g_sel[b * NUM_SELECTED + k];
    const float4* src = keys + ((size_t)b * S + (size_t)blk * BLOCK_SIZE + t) * (D / 4);
    float4* dst = out + (size_t)row * (D / 4);
    dst[threadIdx.x] = src[threadIdx.x];
}

extern "C" void kernel_launch(void* const* d_in, const int* in_sizes, int n_in,
                              void* d_out, int out_size) {
    const float* keys = (const float*)d_in[0];
    const float* scores = (const float*)d_in[1];
    float* out = (float*)d_out;

    topk_kernel<<<B, NB>>>(scores);
    gather_kernel<<<B * NUM_SELECTED * BLOCK_SIZE, D / 4>>>(
        (const float4*)keys, (float4*)out);
}

// round 2
// speedup vs baseline: 1.1096x; 1.1096x over previous
#include <cuda_runtime.h>
#include <stdint.h>

#define BLOCK_SIZE 64
#define NUM_SELECTED 16
#define NB 128          // blocks per batch (8192/64)
#define B 32
#define D 512
#define S 8192

// Each selected block is a contiguous run of BLOCK_SIZE*D floats = 128 KB.
// Split each into SEG_PER_BLK segments handled by one CTA each.
#define SEG_PER_BLK 4
#define THREADS 256
// float4 per segment: (64*512/4) / 4 = 2048 ; per thread: 2048/256 = 8
#define F4_PER_SEG ((BLOCK_SIZE * D / 4) / SEG_PER_BLK)
#define F4_PER_THREAD (F4_PER_SEG / THREADS)

__device__ int g_sel[B * NUM_SELECTED];

// One CTA per batch. Exact rank-based top-k matching jax.lax.top_k ordering:
// descending by value, ties broken by lower index.
__global__ void topk_kernel(const float* __restrict__ scores) {
    int b = blockIdx.x;
    int i = threadIdx.x;  // 0..127
    __shared__ float s[NB];
    float v = scores[b * NB + i];
    s[i] = v;
    __syncthreads();
    int rank = 0;
#pragma unroll 8
    for (int j = 0; j < NB; j++) {
        float sj = s[j];
        rank += (sj > v) || (sj == v && j < i);
    }
    if (rank < NUM_SELECTED) {
        g_sel[b * NUM_SELECTED + rank] = i;
    }
}

// grid = B * NUM_SELECTED * SEG_PER_BLK = 2048 CTAs, 256 threads.
// Each CTA copies a contiguous 32 KB segment with 8 independent float4
// loads per thread (front-batched for MLP).
__global__ void __launch_bounds__(THREADS)
gather_kernel(const float4* __restrict__ keys, float4* __restrict__ out) {
    int cta = blockIdx.x;
    int seg = cta & (SEG_PER_BLK - 1);
    int bk  = cta >> 2;                 // 0..511  (b*16 + k)
    int b   = bk >> 4;
    int blk = __ldg(&g_sel[bk]);

    const float4* src = keys
        + ((size_t)b * S + (size_t)blk * BLOCK_SIZE) * (D / 4)
        + (size_t)seg * F4_PER_SEG;
    float4* dst = out
        + (size_t)bk * (BLOCK_SIZE * D / 4)
        + (size_t)seg * F4_PER_SEG;

    int t = threadIdx.x;
    float4 v[F4_PER_THREAD];
#pragma unroll
    for (int i = 0; i < F4_PER_THREAD; i++)
        v[i] = src[t + i * THREADS];
#pragma unroll
    for (int i = 0; i < F4_PER_THREAD; i++)
        dst[t + i * THREADS] = v[i];
}

extern "C" void kernel_launch(void* const* d_in, const int* in_sizes, int n_in,
                              void* d_out, int out_size) {
    const float* keys = (const float*)d_in[0];
    const float* scores = (const float*)d_in[1];
    float* out = (float*)d_out;

    topk_kernel<<<B, NB>>>(scores);
    gather_kernel<<<B * NUM_SELECTED * SEG_PER_BLK, THREADS>>>(
        (const float4*)keys, (float4*)out);
}

// round 3
// speedup vs baseline: 1.2531x; 1.1293x over previous
#include <cuda_runtime.h>
#include <stdint.h>

#define BLOCK_SIZE 64
#define NUM_SELECTED 16
#define NB 128          // blocks per batch (8192/64)
#define B 32
#define D 512
#define S 8192

#define SEG_PER_BLK 4
#define THREADS 256
// float4 per segment: (64*512/4) / 4 = 2048 ; per thread: 2048/256 = 8
#define F4_PER_SEG ((BLOCK_SIZE * D / 4) / SEG_PER_BLK)
#define F4_PER_THREAD (F4_PER_SEG / THREADS)

// Fused: each CTA recomputes the rank for its (b, k) from the 128 batch
// scores (cheap, L2-hot), then copies its contiguous 32KB segment with
// 8 independent streaming float4 loads/stores per thread.
// grid = B * NUM_SELECTED * SEG_PER_BLK = 2048 CTAs.
__global__ void __launch_bounds__(THREADS)
fused_gather_kernel(const float4* __restrict__ keys,
                    const float* __restrict__ scores,
                    float4* __restrict__ out) {
    int cta = blockIdx.x;
    int seg = cta & (SEG_PER_BLK - 1);
    int bk  = cta >> 2;                 // 0..511  (b*16 + k)
    int b   = bk >> 4;
    int k   = bk & (NUM_SELECTED - 1);

    __shared__ float s[NB];
    __shared__ int blk_s;
    int t = threadIdx.x;

    if (t < NB) s[t] = __ldg(&scores[b * NB + t]);
    __syncthreads();

    // Exact jax.lax.top_k ordering: descending value, ties -> lower index.
    if (t < NB) {
        float v = s[t];
        int rank = 0;
#pragma unroll 8
        for (int j = 0; j < NB; j++) {
            float sj = s[j];
            rank += (sj > v) || (sj == v && j < t);
        }
        if (rank == k) blk_s = t;
    }
    __syncthreads();
    int blk = blk_s;

    const float4* src = keys
        + ((size_t)b * S + (size_t)blk * BLOCK_SIZE) * (D / 4)
        + (size_t)seg * F4_PER_SEG;
    float4* dst = out
        + (size_t)bk * (BLOCK_SIZE * D / 4)
        + (size_t)seg * F4_PER_SEG;

    float4 v[F4_PER_THREAD];
#pragma unroll
    for (int i = 0; i < F4_PER_THREAD; i++)
        v[i] = __ldcs(&src[t + i * THREADS]);   // evict-first: read once
#pragma unroll
    for (int i = 0; i < F4_PER_THREAD; i++)
        __stcs(&dst[t + i * THREADS], v[i]);    // evict-first: write once
}

extern "C" void kernel_launch(void* const* d_in, const int* in_sizes, int n_in,
                              void* d_out, int out_size) {
    const float* keys = (const float*)d_in[0];
    const float* scores = (const float*)d_in[1];
    float* out = (float*)d_out;

    fused_gather_kernel<<<B * NUM_SELECTED * SEG_PER_BLK, THREADS>>>(
        (const float4*)keys, scores, (float4*)out);
}

// round 4
// speedup vs baseline: 1.2688x; 1.0125x over previous
#include <cuda_runtime.h>
#include <stdint.h>

#define BLOCK_SIZE 64
#define NUM_SELECTED 16
#define NB 128          // blocks per batch (8192/64)
#define B 32
#define D 512
#define S 8192

#define SEG_PER_BLK 2
#define THREADS 256
// float4 per block: 64*512/4 = 8192 ; per segment: 4096 ; per thread: 16
#define F4_PER_SEG ((BLOCK_SIZE * D / 4) / SEG_PER_BLK)
#define BATCH 8   // two batches of 8 float4 per thread

// Fused: each CTA recomputes the rank for its (b, k) from the 128 batch
// scores (vectorized, cheap), then streams its contiguous 64 KB segment.
// grid = B * NUM_SELECTED * SEG_PER_BLK = 1024 CTAs.
__global__ void __launch_bounds__(THREADS)
fused_gather_kernel(const float4* __restrict__ keys,
                    const float4* __restrict__ scores4,
                    float4* __restrict__ out) {
    int cta = blockIdx.x;
    int seg = cta & (SEG_PER_BLK - 1);
    int bk  = cta >> 1;                 // 0..511  (b*16 + k)
    int b   = bk >> 4;
    int k   = bk & (NUM_SELECTED - 1);

    __shared__ float4 s4[NB / 4];
    __shared__ int blk_s;
    int t = threadIdx.x;

    if (t < NB / 4) s4[t] = __ldg(&scores4[b * (NB / 4) + t]);
    __syncthreads();

    // Exact jax.lax.top_k ordering: descending value, ties -> lower index.
    if (t < NB) {
        float v = ((const float*)s4)[t];
        int rank = 0;
#pragma unroll
        for (int j4 = 0; j4 < NB / 4; j4++) {
            float4 sj = s4[j4];
            int j = j4 * 4;
            rank += (sj.x > v) || (sj.x == v && (j + 0) < t);
            rank += (sj.y > v) || (sj.y == v && (j + 1) < t);
            rank += (sj.z > v) || (sj.z == v && (j + 2) < t);
            rank += (sj.w > v) || (sj.w == v && (j + 3) < t);
        }
        if (rank == k) blk_s = t;
    }
    __syncthreads();
    int blk = blk_s;

    const float4* src = keys
        + ((size_t)b * S + (size_t)blk * BLOCK_SIZE) * (D / 4)
        + (size_t)seg * F4_PER_SEG;
    float4* dst = out
        + (size_t)bk * (BLOCK_SIZE * D / 4)
        + (size_t)seg * F4_PER_SEG;

    // 16 float4 per thread: two front-batched groups of 8 streaming loads.
    float4 v[BATCH], w[BATCH];
#pragma unroll
    for (int i = 0; i < BATCH; i++)
        v[i] = __ldcs(&src[t + i * THREADS]);
#pragma unroll
    for (int i = 0; i < BATCH; i++)
        w[i] = __ldcs(&src[t + (BATCH + i) * THREADS]);
#pragma unroll
    for (int i = 0; i < BATCH; i++)
        __stcs(&dst[t + i * THREADS], v[i]);
#pragma unroll
    for (int i = 0; i < BATCH; i++)
        __stcs(&dst[t + (BATCH + i) * THREADS], w[i]);
}

extern "C" void kernel_launch(void* const* d_in, const int* in_sizes, int n_in,
                              void* d_out, int out_size) {
    const float* keys = (const float*)d_in[0];
    const float* scores = (const float*)d_in[1];
    float* out = (float*)d_out;

    fused_gather_kernel<<<B * NUM_SELECTED * SEG_PER_BLK, THREADS>>>(
        (const float4*)keys, (const float4*)scores, (float4*)out);
}